// round 6
// baseline (speedup 1.0000x reference)
#include <cuda_runtime.h>
#include <cuda_bf16.h>
#include <cstdint>
#include <cstddef>

// ---------------------------------------------------------------------------
// BiLSTM-NER, Round 5:
//  * lstm_persist: no K-split (8 warps = 4m x 2n-half, all 4 gates per warp
//    via custom ldmatrix lane mapping), cross-step xw prefetch.
//  * mma_gemm: 3-stage cp.async pipeline, 2 CTAs/SM.
//  * All conversions merged into ONE kernel so ncu (-s 5) profiles lstm L1.
// ---------------------------------------------------------------------------

#define Tt 256
#define Bb 256
#define Hh 384
#define G4 1536   // 4*H
#define INP 100
#define Kc 10
#define NCTA_LSTM 96

typedef __nv_bfloat16 bf16;

// ============================ PTX helpers ==================================
__device__ __forceinline__ uint32_t smem_to_u32(const void* p) {
    uint32_t a;
    asm("{ .reg .u64 t; cvta.to.shared.u64 t, %1; cvt.u32.u64 %0, t; }"
        : "=r"(a) : "l"(p));
    return a;
}
__device__ __forceinline__ void ldsm4(uint32_t* r, uint32_t saddr) {
    asm volatile("ldmatrix.sync.aligned.m8n8.x4.shared.b16 {%0,%1,%2,%3}, [%4];"
        : "=r"(r[0]), "=r"(r[1]), "=r"(r[2]), "=r"(r[3]) : "r"(saddr));
}
__device__ __forceinline__ void mma_bf16(float* c, const uint32_t* a, const uint32_t* b) {
    asm volatile(
        "mma.sync.aligned.m16n8k16.row.col.f32.bf16.bf16.f32 "
        "{%0,%1,%2,%3}, {%4,%5,%6,%7}, {%8,%9}, {%0,%1,%2,%3};"
        : "+f"(c[0]), "+f"(c[1]), "+f"(c[2]), "+f"(c[3])
        : "r"(a[0]), "r"(a[1]), "r"(a[2]), "r"(a[3]), "r"(b[0]), "r"(b[1]));
}
#define CP_ASYNC16(sa, ga) \
    asm volatile("cp.async.cg.shared.global [%0], [%1], 16;" \
                 :: "r"(sa), "l"(ga) : "memory")
#define CP_COMMIT() asm volatile("cp.async.commit_group;" ::: "memory")
#define CP_WAIT0()  asm volatile("cp.async.wait_group 0;" ::: "memory")
#define CP_WAIT1()  asm volatile("cp.async.wait_group 1;" ::: "memory")

__device__ __forceinline__ float tanh_ap(float x) {
    float y; asm("tanh.approx.f32 %0, %1;" : "=f"(y) : "f"(x)); return y;
}
__device__ __forceinline__ float sig_ap(float x) {
    return fmaf(tanh_ap(0.5f * x), 0.5f, 0.5f);
}

// ------------------------- scratch (device globals) ------------------------
__device__ float g_xw[(size_t)Tt * Bb * G4];       // gate pre-activations (fp32)
__device__ bf16  g_xb[(size_t)Tt * Bb * 128];      // x padded to K=128, bf16
__device__ bf16  g_h0b[(size_t)Tt * Bb * Hh];      // layer0 outputs (bf16)
__device__ bf16  g_h1b[(size_t)Tt * Bb * Hh];      // layer1 outputs (bf16)
__device__ bf16  g_m1b[(size_t)Tt * Bb * 512];     // MLP hidden 1 (bf16)
__device__ bf16  g_m2b[(size_t)Tt * Bb * 1024];    // MLP hidden 2 (bf16)
__device__ float g_em[(size_t)Tt * Bb * Kc];       // emissions (fp32)
__device__ bf16  g_wih0b[1536 * 128];              // Wih0 padded K=128
__device__ bf16  g_wih1b[1536 * 384];
__device__ bf16  g_w1b[512 * 384];
__device__ bf16  g_w2b[1024 * 512];
__device__ bf16  g_h0buf[2 * Bb * Hh];             // recurrent h state (bf16)
__device__ bf16  g_h1buf[2 * Bb * Hh];
__device__ float g_partial[Bb];

__device__ unsigned int g_arrive[NCTA_LSTM];       // flag-array barrier

// ------------------------------ init state --------------------------------
__global__ void init_state_kernel() {
    int i = blockIdx.x * blockDim.x + threadIdx.x;
    if (i < 2 * Bb * Hh) {
        g_h0buf[i] = __float2bfloat16(0.f);
        g_h1buf[i] = __float2bfloat16(0.f);
    }
    if (i < NCTA_LSTM) g_arrive[i] = 0u;
}

// ---------------------- merged bf16 conversions ----------------------------
// seg0: x (65536 x 100) -> g_xb padded to 128
// seg1: Wih0 (1536 x 100) -> g_wih0b padded to 128
// seg2: Wih1 -> g_wih1b ; seg3: W1 -> g_w1b ; seg4: W2 -> g_w2b
#define S0 (65536 * 128)
#define S1 (1536 * 128)
#define S2 (1536 * 384)
#define S3 (512 * 384)
#define S4 (1024 * 512)
__global__ __launch_bounds__(256) void conv_all(
    const float* __restrict__ x, const float* __restrict__ Wih0,
    const float* __restrict__ Wih1, const float* __restrict__ W1,
    const float* __restrict__ W2)
{
    const int total = S0 + S1 + S2 + S3 + S4;
    for (int i = blockIdx.x * blockDim.x + threadIdx.x; i < total;
         i += gridDim.x * blockDim.x) {
        if (i < S0) {
            int r = i >> 7, c = i & 127;
            g_xb[i] = (c < INP) ? __float2bfloat16(x[(size_t)r * INP + c])
                                : __float2bfloat16(0.f);
        } else if (i < S0 + S1) {
            int j = i - S0;
            int r = j >> 7, c = j & 127;
            g_wih0b[j] = (c < INP) ? __float2bfloat16(Wih0[(size_t)r * INP + c])
                                   : __float2bfloat16(0.f);
        } else if (i < S0 + S1 + S2) {
            int j = i - S0 - S1;
            g_wih1b[j] = __float2bfloat16(Wih1[j]);
        } else if (i < S0 + S1 + S2 + S3) {
            int j = i - S0 - S1 - S2;
            g_w1b[j] = __float2bfloat16(W1[j]);
        } else {
            int j = i - S0 - S1 - S2 - S3;
            g_w2b[j] = __float2bfloat16(W2[j]);
        }
    }
}

// --------------------- flag-array grid barrier -----------------------------
__device__ __forceinline__ void grid_barrier(unsigned int gen) {
    __threadfence();
    __syncthreads();
    if (threadIdx.x == 0)
        *(volatile unsigned int*)&g_arrive[blockIdx.x] = gen;
    if (threadIdx.x < 32) {
#pragma unroll
        for (int i = threadIdx.x; i < NCTA_LSTM; i += 32)
            while (*(volatile unsigned int*)&g_arrive[i] < gen) { }
    }
    __syncthreads();
}

// ======================== HMMA feed-forward GEMM ===========================
// 3-stage cp.async pipeline. CTA 128x128, 8 warps (4m x 2n), 2 CTAs/SM.
__global__ __launch_bounds__(256, 2) void mma_gemm(
    const bf16* __restrict__ A, const bf16* __restrict__ B,
    const float* __restrict__ bias1, const float* __restrict__ bias2,
    float* __restrict__ Cf, bf16* __restrict__ Cb,
    int M, int N, int K)
{
    extern __shared__ bf16 gsm[];          // 3*(128*40) A + 3*(128*40) B
    const uint32_t baseA = smem_to_u32(gsm);
    const uint32_t baseB = baseA + 3 * 5120 * 2;

    const int tid = threadIdx.x;
    const int lane = tid & 31;
    const int wid = tid >> 5;
    const int wm = wid & 3;
    const int wn = wid >> 2;
    const int m0 = blockIdx.y * 128;
    const int n0 = blockIdx.x * 128;

    float acc[2][8][4];
#pragma unroll
    for (int i = 0; i < 2; i++)
#pragma unroll
        for (int j = 0; j < 8; j++)
#pragma unroll
            for (int q = 0; q < 4; q++) acc[i][j][q] = 0.f;

    const uint32_t a_off =
        (uint32_t)(((wm * 32 + (lane & 15)) * 40 + (lane >> 4) * 8) * 2);
    uint32_t b_off[4];
#pragma unroll
    for (int jp = 0; jp < 4; jp++)
        b_off[jp] = (uint32_t)(((wn * 64 + jp * 16 + (lane & 7) + ((lane >> 4) << 3)) * 40
                                + ((lane >> 3) & 1) * 8) * 2);

    const int lrow = tid >> 2;
    const int lc   = tid & 3;
    const uint32_t ld_d = (uint32_t)((lrow * 40 + lc * 8) * 2);
    const uint32_t ld_d2 = (uint32_t)(((lrow + 64) * 40 + lc * 8) * 2);

    const int nkt = K >> 5;

    // prologue: stages 0 and 1
#pragma unroll
    for (int s = 0; s < 2; s++) {
        int k0 = s * 32;
        uint32_t sA = baseA + s * 10240, sB = baseB + s * 10240;
        CP_ASYNC16(sA + ld_d,  A + (size_t)(m0 + lrow) * K + k0 + lc * 8);
        CP_ASYNC16(sA + ld_d2, A + (size_t)(m0 + lrow + 64) * K + k0 + lc * 8);
        CP_ASYNC16(sB + ld_d,  B + (size_t)(n0 + lrow) * K + k0 + lc * 8);
        CP_ASYNC16(sB + ld_d2, B + (size_t)(n0 + lrow + 64) * K + k0 + lc * 8);
        CP_COMMIT();
    }

    int st = 0;                       // stage of kt
    for (int kt = 0; kt < nkt; kt++) {
        CP_WAIT1();
        __syncthreads();

        // issue stage kt+2
        if (kt + 2 < nkt) {
            int s2 = st + 2; if (s2 >= 3) s2 -= 3;
            int k0 = (kt + 2) * 32;
            uint32_t sA = baseA + s2 * 10240, sB = baseB + s2 * 10240;
            CP_ASYNC16(sA + ld_d,  A + (size_t)(m0 + lrow) * K + k0 + lc * 8);
            CP_ASYNC16(sA + ld_d2, A + (size_t)(m0 + lrow + 64) * K + k0 + lc * 8);
            CP_ASYNC16(sB + ld_d,  B + (size_t)(n0 + lrow) * K + k0 + lc * 8);
            CP_ASYNC16(sB + ld_d2, B + (size_t)(n0 + lrow + 64) * K + k0 + lc * 8);
        }
        CP_COMMIT();

        const uint32_t sa = baseA + st * 10240;
        const uint32_t sb = baseB + st * 10240;
#pragma unroll
        for (int kk = 0; kk < 2; kk++) {
            uint32_t a[2][4], b[4][4];
            ldsm4(a[0], sa + a_off + kk * 32);
            ldsm4(a[1], sa + a_off + 1280 + kk * 32);
#pragma unroll
            for (int jp = 0; jp < 4; jp++)
                ldsm4(b[jp], sb + b_off[jp] + kk * 32);
#pragma unroll
            for (int mt = 0; mt < 2; mt++)
#pragma unroll
                for (int j = 0; j < 8; j++)
                    mma_bf16(acc[mt][j], a[mt], &b[j >> 1][(j & 1) * 2]);
        }
        if (++st == 3) st = 0;
    }

#pragma unroll
    for (int mt = 0; mt < 2; mt++)
#pragma unroll
        for (int j = 0; j < 8; j++)
#pragma unroll
            for (int p = 0; p < 2; p++) {
                int row = m0 + wm * 32 + mt * 16 + (lane >> 2) + p * 8;
                int col = n0 + wn * 64 + j * 8 + (lane & 3) * 2;
                float bb0 = bias1[col], bb1 = bias1[col + 1];
                if (bias2) { bb0 += bias2[col]; bb1 += bias2[col + 1]; }
                float v0 = acc[mt][j][p * 2] + bb0;
                float v1 = acc[mt][j][p * 2 + 1] + bb1;
                if (Cf) {
                    *(float2*)(Cf + (size_t)row * N + col) = make_float2(v0, v1);
                } else {
                    *(__nv_bfloat162*)(Cb + (size_t)row * N + col) =
                        __floats2bfloat162_rn(v0, v1);
                }
            }
}

// ===================== persistent HMMA LSTM layer ==========================
// 96 CTAs (4 batch x 24 col groups), 256 threads = 8 warps (4m x 2 hcol-half).
// Each warp: 16 batch rows x 8 h-cols x ALL 4 gates (no K-split, no combine).
// Custom ldmatrix mapping: one ldsm.x4 loads (gate e, gate e+1) 8-row blocks.
__global__ __launch_bounds__(256) void lstm_persist(
    const float* __restrict__ Whh, int layer, unsigned int gen_base)
{
    extern __shared__ bf16 dsm[];
    bf16* Wsm = dsm;                 // 64 x 392 (n = gate*16 + hc)
    bf16* Asm = dsm + 64 * 392;      // 64 x 392 (batch rows)
    const uint32_t wbase = smem_to_u32(Wsm);
    const uint32_t abase = smem_to_u32(Asm);

    const int tid = threadIdx.x;
    const int lane = tid & 31;
    const int wid = tid >> 5;
    const int wm = wid & 3;          // 16-row m tile
    const int wn = wid >> 2;         // h-col half (0/1)
    const int bx = blockIdx.x & 3;
    const int by = blockIdx.x >> 2;
    const int b0 = bx * 64;
    const int c0 = by * 16;

    // resident W slice: Wsm[n][k], n = g*16+hc  <-  Whh[g*384 + c0+hc][k]
    for (int idx = tid; idx < 64 * 384; idx += 256) {
        int n = idx / 384, k = idx - n * 384;
        int g = n >> 4, hc = n & 15;
        Wsm[n * 392 + k] = __float2bfloat16(Whh[(size_t)(g * Hh + c0 + hc) * Hh + k]);
    }

    bf16* hbuf  = layer ? g_h1buf : g_h0buf;
    bf16* houtL = layer ? g_h1b : g_h0b;

    float cst[4] = {0.f, 0.f, 0.f, 0.f};

    // A ldsm: rows wm*16 + (lane&15), k + (lane>>4)*8
    const uint32_t a_off =
        (uint32_t)(((wm * 16 + (lane & 15)) * 392 + (lane >> 4) * 8) * 2);
    // B ldsm lane map: frag0/1 = gate e rows (k0,k8); frag2/3 = gate e+1.
    const uint32_t b_row = ((uint32_t)(lane >> 4) << 4) + wn * 8 + (lane & 7);
    const uint32_t b_k   = ((lane >> 3) & 1) * 8;
    const uint32_t b_off0 = (uint32_t)((b_row * 392 + b_k) * 2);          // gates 0,1
    const uint32_t b_off1 = (uint32_t)(((b_row + 32) * 392 + b_k) * 2);   // gates 2,3

    const int prow = lane >> 2;          // 0..7
    const int pcol = (lane & 3) * 2;     // 0,2,4,6
    const int colg = c0 + wn * 8 + pcol; // h-col of this thread's pair

    grid_barrier(gen_base + 1);   // Wsm resident everywhere; zeros visible

    // preload xw fragments for t = 0
    float2 xv[4][2], xn[4][2];
#pragma unroll
    for (int g = 0; g < 4; g++)
#pragma unroll
        for (int p = 0; p < 2; p++) {
            int brow = b0 + wm * 16 + prow + p * 8;
            xv[g][p] = *(const float2*)(g_xw + (size_t)brow * G4 + g * Hh + colg);
        }

    for (int t = 0; t < Tt; t++) {
        const int phase = t & 1;
        const bf16* hprev = hbuf + (size_t)phase * Bb * Hh;
        bf16* hnext       = hbuf + (size_t)(phase ^ 1) * Bb * Hh;
        bf16* houtp       = houtL + (size_t)t * Bb * Hh;

        // ---- h tile (64 x 384 bf16) via cp.async
#pragma unroll
        for (int it = 0; it < 12; it++) {
            int idx = tid + it * 256;
            int row = idx / 48, c = idx - row * 48;
            CP_ASYNC16(abase + (uint32_t)((row * 392 + c * 8) * 2),
                       hprev + (size_t)(b0 + row) * Hh + c * 8);
        }
        CP_COMMIT(); CP_WAIT0();
        __syncthreads();

        // ---- gates = h_prev @ Whh^T  (24 k-tiles, full K per warp)
        float acc[4][4];
#pragma unroll
        for (int g = 0; g < 4; g++)
#pragma unroll
            for (int q = 0; q < 4; q++) acc[g][q] = 0.f;

#pragma unroll 8
        for (int kt = 0; kt < 24; kt++) {
            uint32_t koff = (uint32_t)(kt * 32);
            uint32_t a[4], bA[4], bB[4];
            ldsm4(a, abase + a_off + koff);
            ldsm4(bA, wbase + b_off0 + koff);
            ldsm4(bB, wbase + b_off1 + koff);
            mma_bf16(acc[0], a, &bA[0]);
            mma_bf16(acc[1], a, &bA[2]);
            mma_bf16(acc[2], a, &bB[0]);
            mma_bf16(acc[3], a, &bB[2]);
        }

        // ---- prefetch xw for t+1 (covers under pointwise + barrier)
        if (t + 1 < Tt) {
            const float* xwn = g_xw + (size_t)(t + 1) * Bb * G4;
#pragma unroll
            for (int g = 0; g < 4; g++)
#pragma unroll
                for (int p = 0; p < 2; p++) {
                    int brow = b0 + wm * 16 + prow + p * 8;
                    xn[g][p] = *(const float2*)(xwn + (size_t)brow * G4 + g * Hh + colg);
                }
        }

        // ---- pointwise LSTM update (each thread: 2 rows x 2 cols)
#pragma unroll
        for (int p = 0; p < 2; p++) {
            int brow = b0 + wm * 16 + prow + p * 8;
            float hnv[2];
#pragma unroll
            for (int q = 0; q < 2; q++) {
                float xi = q ? xv[0][p].y : xv[0][p].x;
                float xf = q ? xv[1][p].y : xv[1][p].x;
                float xg = q ? xv[2][p].y : xv[2][p].x;
                float xo = q ? xv[3][p].y : xv[3][p].x;
                float i_ = sig_ap(acc[0][p * 2 + q] + xi);
                float f_ = sig_ap(acc[1][p * 2 + q] + xf);
                float g_ = tanh_ap(acc[2][p * 2 + q] + xg);
                float o_ = sig_ap(acc[3][p * 2 + q] + xo);
                float cn = f_ * cst[p * 2 + q] + i_ * g_;
                cst[p * 2 + q] = cn;
                hnv[q] = o_ * tanh_ap(cn);
            }
            __nv_bfloat162 hh = __floats2bfloat162_rn(hnv[0], hnv[1]);
            *(__nv_bfloat162*)(hnext + (size_t)brow * Hh + colg) = hh;
            *(__nv_bfloat162*)(houtp + (size_t)brow * Hh + colg) = hh;
        }

        grid_barrier(gen_base + 2 + t);

#pragma unroll
        for (int g = 0; g < 4; g++)
#pragma unroll
            for (int p = 0; p < 2; p++) xv[g][p] = xn[g][p];
    }
}

// ------------------------- emissions (N=10 skinny GEMM) --------------------
__global__ __launch_bounds__(256) void em_kernel(
    const bf16* __restrict__ A, const float* __restrict__ W3,
    const float* __restrict__ b3, float* __restrict__ em)
{
    int row  = blockIdx.x * (blockDim.x >> 5) + (threadIdx.x >> 5);
    int lane = threadIdx.x & 31;
    float acc[Kc];
#pragma unroll
    for (int j = 0; j < Kc; j++) acc[j] = 0.f;
    const __nv_bfloat162* ar = (const __nv_bfloat162*)(A + (size_t)row * 1024);
    for (int k2 = lane; k2 < 512; k2 += 32) {
        float2 a = __bfloat1622float2(ar[k2]);
#pragma unroll
        for (int j = 0; j < Kc; j++) {
            acc[j] += a.x * W3[j * 1024 + 2 * k2] + a.y * W3[j * 1024 + 2 * k2 + 1];
        }
    }
#pragma unroll
    for (int j = 0; j < Kc; j++) {
#pragma unroll
        for (int off = 16; off; off >>= 1)
            acc[j] += __shfl_xor_sync(0xffffffffu, acc[j], off);
    }
    if (lane == 0) {
#pragma unroll
        for (int j = 0; j < Kc; j++) em[(size_t)row * Kc + j] = acc[j] + b3[j];
    }
}

// ------------------------------ CRF ----------------------------------------
__global__ __launch_bounds__(32) void crf_kernel(
    const float* __restrict__ em, const int* __restrict__ tags,
    const float* __restrict__ start_t, const float* __restrict__ end_t,
    const float* __restrict__ trans)
{
    const int bp   = blockIdx.x;
    const int lane = threadIdx.x;
    const float NEG = -1e30f;

    float tr[Kc];
    int cl = (lane < Kc) ? lane : 0;
#pragma unroll
    for (int i = 0; i < Kc; i++) tr[i] = trans[i * Kc + cl];

    float a = (lane < Kc) ? (start_t[lane] + em[((size_t)bp * Tt) * Kc + lane]) : NEG;

    for (int tp = 1; tp < Tt; tp++) {
        float e = (lane < Kc) ? em[((size_t)bp * Tt + tp) * Kc + lane] : 0.f;
        float v[Kc];
        float m = NEG;
#pragma unroll
        for (int i = 0; i < Kc; i++) {
            float ai = __shfl_sync(0xffffffffu, a, i);
            v[i] = ai + tr[i];
            m = fmaxf(m, v[i]);
        }
        float s = 0.f;
#pragma unroll
        for (int i = 0; i < Kc; i++) s += __expf(v[i] - m);
        float an = m + __logf(s) + e;
        a = (lane < Kc) ? an : NEG;
    }

    float z = (lane < Kc) ? (a + end_t[lane]) : NEG;
    float zmax = z;
#pragma unroll
    for (int off = 16; off; off >>= 1)
        zmax = fmaxf(zmax, __shfl_xor_sync(0xffffffffu, zmax, off));
    float zs = (lane < Kc) ? __expf(z - zmax) : 0.f;
#pragma unroll
    for (int off = 16; off; off >>= 1)
        zs += __shfl_xor_sync(0xffffffffu, zs, off);
    float logZ = zmax + __logf(zs);

    if (lane == 0) {
        int prev = tags[(size_t)bp * Tt];
        float score = start_t[prev] + em[((size_t)bp * Tt) * Kc + prev];
        for (int tp = 1; tp < Tt; tp++) {
            int tg = tags[(size_t)bp * Tt + tp];
            score += trans[prev * Kc + tg] + em[((size_t)bp * Tt + tp) * Kc + tg];
            prev = tg;
        }
        score += end_t[prev];
        g_partial[bp] = logZ - score;
    }
}

__global__ __launch_bounds__(256) void reduce_kernel(float* __restrict__ out)
{
    __shared__ float sh[256];
    int i = threadIdx.x;
    sh[i] = g_partial[i];
    __syncthreads();
#pragma unroll
    for (int s = 128; s; s >>= 1) {
        if (i < s) sh[i] += sh[i + s];
        __syncthreads();
    }
    if (i == 0) out[0] = sh[0];
}

// ------------------------------ launch -------------------------------------
extern "C" void kernel_launch(void* const* d_in, const int* in_sizes, int n_in,
                              void* d_out, int out_size)
{
    (void)in_sizes; (void)n_in; (void)out_size;
    const float* x    = (const float*)d_in[0];
    const int*   tags = (const int*)d_in[2];
    const float* Wih0 = (const float*)d_in[3];
    const float* Whh0 = (const float*)d_in[4];
    const float* bih0 = (const float*)d_in[5];
    const float* bhh0 = (const float*)d_in[6];
    const float* Wih1 = (const float*)d_in[7];
    const float* Whh1 = (const float*)d_in[8];
    const float* bih1 = (const float*)d_in[9];
    const float* bhh1 = (const float*)d_in[10];
    const float* W1   = (const float*)d_in[11];
    const float* b1   = (const float*)d_in[12];
    const float* W2   = (const float*)d_in[13];
    const float* b2   = (const float*)d_in[14];
    const float* W3   = (const float*)d_in[15];
    const float* b3   = (const float*)d_in[16];
    const float* st   = (const float*)d_in[17];
    const float* et   = (const float*)d_in[18];
    const float* trn  = (const float*)d_in[19];

    float *xw, *emb;
    bf16 *xb, *h0b, *h1b, *m1b, *m2b, *wih0b, *wih1b, *w1b, *w2b;
    cudaGetSymbolAddress((void**)&xw,    g_xw);
    cudaGetSymbolAddress((void**)&emb,   g_em);
    cudaGetSymbolAddress((void**)&xb,    g_xb);
    cudaGetSymbolAddress((void**)&h0b,   g_h0b);
    cudaGetSymbolAddress((void**)&h1b,   g_h1b);
    cudaGetSymbolAddress((void**)&m1b,   g_m1b);
    cudaGetSymbolAddress((void**)&m2b,   g_m2b);
    cudaGetSymbolAddress((void**)&wih0b, g_wih0b);
    cudaGetSymbolAddress((void**)&wih1b, g_wih1b);
    cudaGetSymbolAddress((void**)&w1b,   g_w1b);
    cudaGetSymbolAddress((void**)&w2b,   g_w2b);

    const int M = Tt * Bb;  // 65536
    const size_t LSTM_SMEM = (size_t)(2 * 64 * 392) * sizeof(bf16);  // 100352 B
    const size_t GEMM_SMEM = (size_t)(6 * 128 * 40) * sizeof(bf16);  // 61440 B
    cudaFuncSetAttribute(lstm_persist, cudaFuncAttributeMaxDynamicSharedMemorySize,
                         (int)LSTM_SMEM);
    cudaFuncSetAttribute(mma_gemm, cudaFuncAttributeMaxDynamicSharedMemorySize,
                         (int)GEMM_SMEM);

    // launch order matters for ncu (-s 5 profiles launch #5 = lstm layer 1)
    init_state_kernel<<<(2 * Bb * Hh + 255) / 256, 256>>>();                 // 0
    conv_all<<<8192, 256>>>(x, Wih0, Wih1, W1, W2);                          // 1

    mma_gemm<<<dim3(G4 / 128, M / 128), 256, GEMM_SMEM>>>(                   // 2
        xb, wih0b, bih0, bhh0, xw, nullptr, M, G4, 128);
    lstm_persist<<<NCTA_LSTM, 256, LSTM_SMEM>>>(Whh0, 0, 0u);                // 3

    mma_gemm<<<dim3(G4 / 128, M / 128), 256, GEMM_SMEM>>>(                   // 4
        h0b, wih1b, bih1, bhh1, xw, nullptr, M, G4, Hh);
    lstm_persist<<<NCTA_LSTM, 256, LSTM_SMEM>>>(Whh1, 1, 257u);              // 5

    mma_gemm<<<dim3(512 / 128, M / 128), 256, GEMM_SMEM>>>(                  // 6
        h1b, w1b, b1, nullptr, nullptr, m1b, M, 512, Hh);
    mma_gemm<<<dim3(1024 / 128, M / 128), 256, GEMM_SMEM>>>(                 // 7
        m1b, w2b, b2, nullptr, nullptr, m2b, M, 1024, 512);
    em_kernel<<<M / 8, 256>>>(m2b, W3, b3, emb);                             // 8

    crf_kernel<<<Bb, 32>>>(emb, tags, st, et, trn);                          // 9
    reduce_kernel<<<1, 256>>>((float*)d_out);                                // 10
}

// round 7
// speedup vs baseline: 1.6987x; 1.6987x over previous
#include <cuda_runtime.h>
#include <cuda_bf16.h>
#include <cstdint>
#include <cstddef>

// ---------------------------------------------------------------------------
// BiLSTM-NER, Round 6: revert to R3-proven components (2-stage HMMA GEMM,
// atomic-counter grid barrier, 4-warp full-K LSTM microkernel) + ONE
// structural change: both LSTM layers fused into a single persistent kernel,
// pipelined (interval t = L0 step t + L1 step t-1, sharing the h0(t-1) tile).
// The h0@Wih1 inter-layer GEMM and g_xw round trip for layer 1 are gone;
// grid barriers drop 514 -> 257.
// ---------------------------------------------------------------------------

#define Tt 256
#define Bb 256
#define Hh 384
#define G4 1536   // 4*H
#define INP 100
#define Kc 10
#define NCTA_LSTM 96

typedef __nv_bfloat16 bf16;

// ============================ PTX helpers ==================================
__device__ __forceinline__ uint32_t smem_to_u32(const void* p) {
    uint32_t a;
    asm("{ .reg .u64 t; cvta.to.shared.u64 t, %1; cvt.u32.u64 %0, t; }"
        : "=r"(a) : "l"(p));
    return a;
}
__device__ __forceinline__ void ldsm4(uint32_t* r, uint32_t saddr) {
    asm volatile("ldmatrix.sync.aligned.m8n8.x4.shared.b16 {%0,%1,%2,%3}, [%4];"
        : "=r"(r[0]), "=r"(r[1]), "=r"(r[2]), "=r"(r[3]) : "r"(saddr));
}
__device__ __forceinline__ void mma_bf16(float* c, const uint32_t* a, const uint32_t* b) {
    asm volatile(
        "mma.sync.aligned.m16n8k16.row.col.f32.bf16.bf16.f32 "
        "{%0,%1,%2,%3}, {%4,%5,%6,%7}, {%8,%9}, {%0,%1,%2,%3};"
        : "+f"(c[0]), "+f"(c[1]), "+f"(c[2]), "+f"(c[3])
        : "r"(a[0]), "r"(a[1]), "r"(a[2]), "r"(a[3]), "r"(b[0]), "r"(b[1]));
}
#define CP_ASYNC16(sa, ga) \
    asm volatile("cp.async.cg.shared.global [%0], [%1], 16;" \
                 :: "r"(sa), "l"(ga) : "memory")
#define CP_COMMIT() asm volatile("cp.async.commit_group;" ::: "memory")
#define CP_WAIT0()  asm volatile("cp.async.wait_group 0;" ::: "memory")

__device__ __forceinline__ float tanh_ap(float x) {
    float y; asm("tanh.approx.f32 %0, %1;" : "=f"(y) : "f"(x)); return y;
}
__device__ __forceinline__ float sig_ap(float x) {
    return fmaf(tanh_ap(0.5f * x), 0.5f, 0.5f);
}

// ------------------------- scratch (device globals) ------------------------
__device__ float g_xw[(size_t)Tt * Bb * G4];       // layer-0 gate pre-acts (fp32)
__device__ bf16  g_xb[(size_t)Tt * Bb * 128];      // x padded to K=128, bf16
__device__ bf16  g_h1b[(size_t)Tt * Bb * Hh];      // layer1 outputs (bf16)
__device__ bf16  g_m1b[(size_t)Tt * Bb * 512];     // MLP hidden 1 (bf16)
__device__ bf16  g_m2b[(size_t)Tt * Bb * 1024];    // MLP hidden 2 (bf16)
__device__ float g_em[(size_t)Tt * Bb * Kc];       // emissions (fp32)
__device__ bf16  g_wih0b[1536 * 128];              // Wih0 padded K=128
__device__ bf16  g_w1b[512 * 384];
__device__ bf16  g_w2b[1024 * 512];
__device__ bf16  g_h0buf[2 * Bb * Hh];             // recurrent h0 state (bf16)
__device__ bf16  g_h1buf[2 * Bb * Hh];             // recurrent h1 state (bf16)
__device__ float g_partial[Bb];

__device__ unsigned int g_barcnt;
__device__ volatile unsigned int g_bargen;

// ------------------------------ init state --------------------------------
__global__ void init_state_kernel() {
    int i = blockIdx.x * blockDim.x + threadIdx.x;
    if (i < 2 * Bb * Hh) {
        g_h0buf[i] = __float2bfloat16(0.f);
        g_h1buf[i] = __float2bfloat16(0.f);
    }
    if (i == 0) { g_barcnt = 0; g_bargen = 0; }
}

// ---------------------- merged bf16 conversions ----------------------------
#define S0 (65536 * 128)
#define S1 (1536 * 128)
#define S3 (512 * 384)
#define S4 (1024 * 512)
__global__ __launch_bounds__(256) void conv_all(
    const float* __restrict__ x, const float* __restrict__ Wih0,
    const float* __restrict__ W1, const float* __restrict__ W2)
{
    const int total = S0 + S1 + S3 + S4;
    for (int i = blockIdx.x * blockDim.x + threadIdx.x; i < total;
         i += gridDim.x * blockDim.x) {
        if (i < S0) {
            int r = i >> 7, c = i & 127;
            g_xb[i] = (c < INP) ? __float2bfloat16(x[(size_t)r * INP + c])
                                : __float2bfloat16(0.f);
        } else if (i < S0 + S1) {
            int j = i - S0;
            int r = j >> 7, c = j & 127;
            g_wih0b[j] = (c < INP) ? __float2bfloat16(Wih0[(size_t)r * INP + c])
                                   : __float2bfloat16(0.f);
        } else if (i < S0 + S1 + S3) {
            int j = i - S0 - S1;
            g_w1b[j] = __float2bfloat16(W1[j]);
        } else {
            int j = i - S0 - S1 - S3;
            g_w2b[j] = __float2bfloat16(W2[j]);
        }
    }
}

// --------------------- atomic-counter grid barrier (R3-proven) -------------
__device__ __forceinline__ void grid_barrier() {
    __threadfence();
    __syncthreads();
    if (threadIdx.x == 0) {
        unsigned int gen = g_bargen;
        if (atomicAdd(&g_barcnt, 1u) == NCTA_LSTM - 1) {
            g_barcnt = 0;
            __threadfence();
            g_bargen = gen + 1;
        } else {
            while (g_bargen == gen) { }
        }
    }
    __syncthreads();
}

// ======================== HMMA feed-forward GEMM (R3) ======================
__global__ __launch_bounds__(256) void mma_gemm(
    const bf16* __restrict__ A, const bf16* __restrict__ B,
    const float* __restrict__ bias1, const float* __restrict__ bias2,
    float* __restrict__ Cf, bf16* __restrict__ Cb,
    int M, int N, int K)
{
    __shared__ __align__(16) bf16 smA[2][128 * 40];
    __shared__ __align__(16) bf16 smB[2][128 * 40];

    const int tid = threadIdx.x;
    const int lane = tid & 31;
    const int wid = tid >> 5;
    const int wm = wid & 3;
    const int wn = wid >> 2;
    const int m0 = blockIdx.y * 128;
    const int n0 = blockIdx.x * 128;

    const uint32_t saddrA[2] = { smem_to_u32(smA[0]), smem_to_u32(smA[1]) };
    const uint32_t saddrB[2] = { smem_to_u32(smB[0]), smem_to_u32(smB[1]) };

    float acc[2][8][4];
#pragma unroll
    for (int i = 0; i < 2; i++)
#pragma unroll
        for (int j = 0; j < 8; j++)
#pragma unroll
            for (int q = 0; q < 4; q++) acc[i][j][q] = 0.f;

    const uint32_t a_off =
        (uint32_t)(((wm * 32 + (lane & 15)) * 40 + (lane >> 4) * 8) * 2);
    uint32_t b_off[4];
#pragma unroll
    for (int jp = 0; jp < 4; jp++)
        b_off[jp] = (uint32_t)(((wn * 64 + jp * 16 + (lane & 7) + ((lane >> 4) << 3)) * 40
                                + ((lane >> 3) & 1) * 8) * 2);

    const int lrow = tid >> 2;
    const int lc   = tid & 3;

    const int nkt = K >> 5;
#pragma unroll
    for (int it = 0; it < 2; it++) {
        int row = lrow + it * 64;
        uint32_t d = (uint32_t)((row * 40 + lc * 8) * 2);
        CP_ASYNC16(saddrA[0] + d, A + (size_t)(m0 + row) * K + lc * 8);
        CP_ASYNC16(saddrB[0] + d, B + (size_t)(n0 + row) * K + lc * 8);
    }
    CP_COMMIT();

    for (int kt = 0; kt < nkt; kt++) {
        CP_WAIT0();
        __syncthreads();
        if (kt + 1 < nkt) {
            int s = (kt + 1) & 1;
            int k0 = (kt + 1) * 32;
#pragma unroll
            for (int it = 0; it < 2; it++) {
                int row = lrow + it * 64;
                uint32_t d = (uint32_t)((row * 40 + lc * 8) * 2);
                CP_ASYNC16(saddrA[s] + d, A + (size_t)(m0 + row) * K + k0 + lc * 8);
                CP_ASYNC16(saddrB[s] + d, B + (size_t)(n0 + row) * K + k0 + lc * 8);
            }
        }
        CP_COMMIT();

        const uint32_t sa = saddrA[kt & 1];
        const uint32_t sb = saddrB[kt & 1];
#pragma unroll
        for (int kk = 0; kk < 2; kk++) {
            uint32_t a[2][4], b[4][4];
            ldsm4(a[0], sa + a_off + kk * 32);
            ldsm4(a[1], sa + a_off + 1280 + kk * 32);
#pragma unroll
            for (int jp = 0; jp < 4; jp++)
                ldsm4(b[jp], sb + b_off[jp] + kk * 32);
#pragma unroll
            for (int mt = 0; mt < 2; mt++)
#pragma unroll
                for (int j = 0; j < 8; j++)
                    mma_bf16(acc[mt][j], a[mt], &b[j >> 1][(j & 1) * 2]);
        }
        __syncthreads();
    }

#pragma unroll
    for (int mt = 0; mt < 2; mt++)
#pragma unroll
        for (int j = 0; j < 8; j++)
#pragma unroll
            for (int p = 0; p < 2; p++) {
                int row = m0 + wm * 32 + mt * 16 + (lane >> 2) + p * 8;
                int col = n0 + wn * 64 + j * 8 + (lane & 3) * 2;
                float bb0 = bias1[col], bb1 = bias1[col + 1];
                if (bias2) { bb0 += bias2[col]; bb1 += bias2[col + 1]; }
                float v0 = acc[mt][j][p * 2] + bb0;
                float v1 = acc[mt][j][p * 2 + 1] + bb1;
                if (Cf) {
                    *(float2*)(Cf + (size_t)row * N + col) = make_float2(v0, v1);
                } else {
                    *(__nv_bfloat162*)(Cb + (size_t)row * N + col) =
                        __floats2bfloat162_rn(v0, v1);
                }
            }
}

// ================== fused 2-layer persistent LSTM ==========================
// 96 CTAs (4 batch x 24 colgroups), 128 threads (4 warps, 16 rows each).
// Interval t (0..256): L0 step t  (uses h0(t-1), xw0(t), Whh0)
//                      L1 step t-1 (uses h0(t-1)@Wih1 + h1(t-2)@Whh1 + bias)
// Resident SMEM: Whh0/Wih1/Whh1 slices (64n x 392 bf16 each) + 1 A tile.
__device__ __forceinline__ void mma_pass24(
    float (*acc)[4], uint32_t a_base, uint32_t w_base,
    uint32_t a_off, const uint32_t* b_off)
{
#pragma unroll 6
    for (int kt = 0; kt < 24; kt++) {
        uint32_t koff = (uint32_t)(kt * 32);
        uint32_t a[4], b[4][4];
        ldsm4(a, a_base + a_off + koff);
#pragma unroll
        for (int jp = 0; jp < 4; jp++)
            ldsm4(b[jp], w_base + b_off[jp] + koff);
#pragma unroll
        for (int j = 0; j < 8; j++)
            mma_bf16(acc[j], a, &b[j >> 1][(j & 1) * 2]);
    }
}

__global__ __launch_bounds__(128) void lstm_fused(
    const float* __restrict__ Whh0, const float* __restrict__ Wih1,
    const float* __restrict__ Whh1, const float* __restrict__ bih1,
    const float* __restrict__ bhh1)
{
    extern __shared__ bf16 dsm[];
    bf16* W0sm  = dsm;                    // Whh0 slice  (64 x 392)
    bf16* Wi1sm = dsm + 64 * 392;         // Wih1 slice
    bf16* W1sm  = dsm + 2 * 64 * 392;     // Whh1 slice
    bf16* Asm   = dsm + 3 * 64 * 392;     // shared A tile (64 x 392)
    const uint32_t w0base  = smem_to_u32(W0sm);
    const uint32_t wi1base = smem_to_u32(Wi1sm);
    const uint32_t w1base  = smem_to_u32(W1sm);
    const uint32_t abase   = smem_to_u32(Asm);

    const int tid = threadIdx.x;
    const int lane = tid & 31;
    const int w4 = tid >> 5;             // warp = 16-row m tile
    const int bx = blockIdx.x & 3;
    const int by = blockIdx.x >> 2;
    const int b0 = bx * 64;
    const int c0 = by * 16;

    // ---- load 3 resident W slices: [n][k], n = g*16+hc
    for (int idx = tid; idx < 64 * 384; idx += 128) {
        int n = idx / 384, k = idx - n * 384;
        int g = n >> 4, hc = n & 15;
        size_t grow = (size_t)(g * Hh + c0 + hc) * Hh + k;
        int d = n * 392 + k;
        W0sm[d]  = __float2bfloat16(Whh0[grow]);
        Wi1sm[d] = __float2bfloat16(Wih1[grow]);
        W1sm[d]  = __float2bfloat16(Whh1[grow]);
    }

    // ldmatrix offsets (stride 392 bf16 = 784 B)
    const uint32_t a_off =
        (uint32_t)(((w4 * 16 + (lane & 15)) * 392 + (lane >> 4) * 8) * 2);
    uint32_t b_off[4];
#pragma unroll
    for (int jp = 0; jp < 4; jp++)
        b_off[jp] = (uint32_t)(((jp * 16 + (lane & 7) + ((lane >> 4) << 3)) * 392
                                + ((lane >> 3) & 1) * 8) * 2);

    const int prow = lane >> 2;          // 0..7
    const int pcol = (lane & 3) * 2;     // 0,2,4,6

    // layer-1 bias (bih1 + bhh1) for this thread's gate columns
    float bi1[4][2][2];
#pragma unroll
    for (int g = 0; g < 4; g++)
#pragma unroll
        for (int hb = 0; hb < 2; hb++)
#pragma unroll
            for (int q = 0; q < 2; q++) {
                int col = c0 + hb * 8 + pcol + q;
                bi1[g][hb][q] = bih1[g * Hh + col] + bhh1[g * Hh + col];
            }

    float cst0[8], cst1[8];
#pragma unroll
    for (int i = 0; i < 8; i++) { cst0[i] = 0.f; cst1[i] = 0.f; }

    grid_barrier();   // all W slices resident; zeroed h buffers visible

    for (int t = 0; t <= Tt; t++) {
        const int ph = t & 1;
        const bool doL0 = (t < Tt);
        const bool doL1 = (t >= 1);

        // ---- xw0(t) fragments for L0 pointwise
        float2 xv[8][2];
        if (doL0) {
            const float* xw = g_xw + (size_t)t * Bb * G4;
#pragma unroll
            for (int j = 0; j < 8; j++)
#pragma unroll
                for (int p = 0; p < 2; p++) {
                    int brow = b0 + w4 * 16 + prow + p * 8;
                    int col = (j >> 1) * Hh + c0 + ((j & 1) << 3) + pcol;
                    xv[j][p] = *(const float2*)(xw + (size_t)brow * G4 + col);
                }
        }

        // ---- load A = h0(t-1) tile (shared by L0 recurrence and L1 input)
        {
            const bf16* hprev0 = g_h0buf + (size_t)ph * Bb * Hh;
#pragma unroll
            for (int it = 0; it < 24; it++) {
                int idx = tid + it * 128;
                int row = idx / 48, c = idx - row * 48;
                CP_ASYNC16(abase + (uint32_t)((row * 392 + c * 8) * 2),
                           hprev0 + (size_t)(b0 + row) * Hh + c * 8);
            }
            CP_COMMIT(); CP_WAIT0();
            __syncthreads();
        }

        float accL0[8][4], accL1[8][4];
#pragma unroll
        for (int j = 0; j < 8; j++)
#pragma unroll
            for (int q = 0; q < 4; q++) { accL0[j][q] = 0.f; accL1[j][q] = 0.f; }

        if (doL0) mma_pass24(accL0, abase, w0base,  a_off, b_off);
        if (doL1) mma_pass24(accL1, abase, wi1base, a_off, b_off);
        __syncthreads();    // everyone done reading Asm

        // ---- issue A = h1(t-2) tile load; overlap with L0 pointwise
        if (doL1) {
            const bf16* hprev1 = g_h1buf + (size_t)ph * Bb * Hh;
#pragma unroll
            for (int it = 0; it < 24; it++) {
                int idx = tid + it * 128;
                int row = idx / 48, c = idx - row * 48;
                CP_ASYNC16(abase + (uint32_t)((row * 392 + c * 8) * 2),
                           hprev1 + (size_t)(b0 + row) * Hh + c * 8);
            }
            CP_COMMIT();
        }

        // ---- L0 pointwise: h0(t) -> h0buf[ph^1]
        if (doL0) {
            bf16* hnext0 = g_h0buf + (size_t)(ph ^ 1) * Bb * Hh;
#pragma unroll
            for (int p = 0; p < 2; p++) {
                int brow = b0 + w4 * 16 + prow + p * 8;
#pragma unroll
                for (int hb = 0; hb < 2; hb++) {
                    float hnv[2];
#pragma unroll
                    for (int q = 0; q < 2; q++) {
                        float xi = q ? xv[0 + hb][p].y : xv[0 + hb][p].x;
                        float xf = q ? xv[2 + hb][p].y : xv[2 + hb][p].x;
                        float xg = q ? xv[4 + hb][p].y : xv[4 + hb][p].x;
                        float xo = q ? xv[6 + hb][p].y : xv[6 + hb][p].x;
                        float i_ = sig_ap(accL0[0 + hb][p * 2 + q] + xi);
                        float f_ = sig_ap(accL0[2 + hb][p * 2 + q] + xf);
                        float g_ = tanh_ap(accL0[4 + hb][p * 2 + q] + xg);
                        float o_ = sig_ap(accL0[6 + hb][p * 2 + q] + xo);
                        int ci = p * 4 + hb * 2 + q;
                        float cn = f_ * cst0[ci] + i_ * g_;
                        cst0[ci] = cn;
                        hnv[q] = o_ * tanh_ap(cn);
                    }
                    int cg = c0 + hb * 8 + pcol;
                    *(__nv_bfloat162*)(hnext0 + (size_t)brow * Hh + cg) =
                        __floats2bfloat162_rn(hnv[0], hnv[1]);
                }
            }
        }

        // ---- L1 recurrence mma + pointwise: h1(t-1)
        if (doL1) {
            CP_WAIT0();
            __syncthreads();
            mma_pass24(accL1, abase, w1base, a_off, b_off);

            bf16* hnext1 = g_h1buf + (size_t)(ph ^ 1) * Bb * Hh;
            bf16* houtp  = g_h1b + (size_t)(t - 1) * Bb * Hh;
#pragma unroll
            for (int p = 0; p < 2; p++) {
                int brow = b0 + w4 * 16 + prow + p * 8;
#pragma unroll
                for (int hb = 0; hb < 2; hb++) {
                    float hnv[2];
#pragma unroll
                    for (int q = 0; q < 2; q++) {
                        float i_ = sig_ap(accL1[0 + hb][p * 2 + q] + bi1[0][hb][q]);
                        float f_ = sig_ap(accL1[2 + hb][p * 2 + q] + bi1[1][hb][q]);
                        float g_ = tanh_ap(accL1[4 + hb][p * 2 + q] + bi1[2][hb][q]);
                        float o_ = sig_ap(accL1[6 + hb][p * 2 + q] + bi1[3][hb][q]);
                        int ci = p * 4 + hb * 2 + q;
                        float cn = f_ * cst1[ci] + i_ * g_;
                        cst1[ci] = cn;
                        hnv[q] = o_ * tanh_ap(cn);
                    }
                    int cg = c0 + hb * 8 + pcol;
                    __nv_bfloat162 hh = __floats2bfloat162_rn(hnv[0], hnv[1]);
                    *(__nv_bfloat162*)(hnext1 + (size_t)brow * Hh + cg) = hh;
                    *(__nv_bfloat162*)(houtp + (size_t)brow * Hh + cg) = hh;
                }
            }
        }

        grid_barrier();
    }
}

// ------------------------- emissions (N=10 skinny GEMM) --------------------
__global__ __launch_bounds__(256) void em_kernel(
    const bf16* __restrict__ A, const float* __restrict__ W3,
    const float* __restrict__ b3, float* __restrict__ em)
{
    int row  = blockIdx.x * (blockDim.x >> 5) + (threadIdx.x >> 5);
    int lane = threadIdx.x & 31;
    float acc[Kc];
#pragma unroll
    for (int j = 0; j < Kc; j++) acc[j] = 0.f;
    const __nv_bfloat162* ar = (const __nv_bfloat162*)(A + (size_t)row * 1024);
    for (int k2 = lane; k2 < 512; k2 += 32) {
        float2 a = __bfloat1622float2(ar[k2]);
#pragma unroll
        for (int j = 0; j < Kc; j++) {
            acc[j] += a.x * W3[j * 1024 + 2 * k2] + a.y * W3[j * 1024 + 2 * k2 + 1];
        }
    }
#pragma unroll
    for (int j = 0; j < Kc; j++) {
#pragma unroll
        for (int off = 16; off; off >>= 1)
            acc[j] += __shfl_xor_sync(0xffffffffu, acc[j], off);
    }
    if (lane == 0) {
#pragma unroll
        for (int j = 0; j < Kc; j++) em[(size_t)row * Kc + j] = acc[j] + b3[j];
    }
}

// ------------------------------ CRF ----------------------------------------
__global__ __launch_bounds__(32) void crf_kernel(
    const float* __restrict__ em, const int* __restrict__ tags,
    const float* __restrict__ start_t, const float* __restrict__ end_t,
    const float* __restrict__ trans)
{
    const int bp   = blockIdx.x;
    const int lane = threadIdx.x;
    const float NEG = -1e30f;

    float tr[Kc];
    int cl = (lane < Kc) ? lane : 0;
#pragma unroll
    for (int i = 0; i < Kc; i++) tr[i] = trans[i * Kc + cl];

    float a = (lane < Kc) ? (start_t[lane] + em[((size_t)bp * Tt) * Kc + lane]) : NEG;

    for (int tp = 1; tp < Tt; tp++) {
        float e = (lane < Kc) ? em[((size_t)bp * Tt + tp) * Kc + lane] : 0.f;
        float v[Kc];
        float m = NEG;
#pragma unroll
        for (int i = 0; i < Kc; i++) {
            float ai = __shfl_sync(0xffffffffu, a, i);
            v[i] = ai + tr[i];
            m = fmaxf(m, v[i]);
        }
        float s = 0.f;
#pragma unroll
        for (int i = 0; i < Kc; i++) s += __expf(v[i] - m);
        float an = m + __logf(s) + e;
        a = (lane < Kc) ? an : NEG;
    }

    float z = (lane < Kc) ? (a + end_t[lane]) : NEG;
    float zmax = z;
#pragma unroll
    for (int off = 16; off; off >>= 1)
        zmax = fmaxf(zmax, __shfl_xor_sync(0xffffffffu, zmax, off));
    float zs = (lane < Kc) ? __expf(z - zmax) : 0.f;
#pragma unroll
    for (int off = 16; off; off >>= 1)
        zs += __shfl_xor_sync(0xffffffffu, zs, off);
    float logZ = zmax + __logf(zs);

    if (lane == 0) {
        int prev = tags[(size_t)bp * Tt];
        float score = start_t[prev] + em[((size_t)bp * Tt) * Kc + prev];
        for (int tp = 1; tp < Tt; tp++) {
            int tg = tags[(size_t)bp * Tt + tp];
            score += trans[prev * Kc + tg] + em[((size_t)bp * Tt + tp) * Kc + tg];
            prev = tg;
        }
        score += end_t[prev];
        g_partial[bp] = logZ - score;
    }
}

__global__ __launch_bounds__(256) void reduce_kernel(float* __restrict__ out)
{
    __shared__ float sh[256];
    int i = threadIdx.x;
    sh[i] = g_partial[i];
    __syncthreads();
#pragma unroll
    for (int s = 128; s; s >>= 1) {
        if (i < s) sh[i] += sh[i + s];
        __syncthreads();
    }
    if (i == 0) out[0] = sh[0];
}

// ------------------------------ launch -------------------------------------
extern "C" void kernel_launch(void* const* d_in, const int* in_sizes, int n_in,
                              void* d_out, int out_size)
{
    (void)in_sizes; (void)n_in; (void)out_size;
    const float* x    = (const float*)d_in[0];
    const int*   tags = (const int*)d_in[2];
    const float* Wih0 = (const float*)d_in[3];
    const float* Whh0 = (const float*)d_in[4];
    const float* bih0 = (const float*)d_in[5];
    const float* bhh0 = (const float*)d_in[6];
    const float* Wih1 = (const float*)d_in[7];
    const float* Whh1 = (const float*)d_in[8];
    const float* bih1 = (const float*)d_in[9];
    const float* bhh1 = (const float*)d_in[10];
    const float* W1   = (const float*)d_in[11];
    const float* b1   = (const float*)d_in[12];
    const float* W2   = (const float*)d_in[13];
    const float* b2   = (const float*)d_in[14];
    const float* W3   = (const float*)d_in[15];
    const float* b3   = (const float*)d_in[16];
    const float* st   = (const float*)d_in[17];
    const float* et   = (const float*)d_in[18];
    const float* trn  = (const float*)d_in[19];

    float *xw, *emb;
    bf16 *xb, *h1b, *m1b, *m2b, *wih0b, *w1b, *w2b;
    cudaGetSymbolAddress((void**)&xw,    g_xw);
    cudaGetSymbolAddress((void**)&emb,   g_em);
    cudaGetSymbolAddress((void**)&xb,    g_xb);
    cudaGetSymbolAddress((void**)&h1b,   g_h1b);
    cudaGetSymbolAddress((void**)&m1b,   g_m1b);
    cudaGetSymbolAddress((void**)&m2b,   g_m2b);
    cudaGetSymbolAddress((void**)&wih0b, g_wih0b);
    cudaGetSymbolAddress((void**)&w1b,   g_w1b);
    cudaGetSymbolAddress((void**)&w2b,   g_w2b);

    const int M = Tt * Bb;  // 65536
    const size_t LSTM_SMEM = (size_t)(4 * 64 * 392) * sizeof(bf16);  // 200704 B
    cudaFuncSetAttribute(lstm_fused, cudaFuncAttributeMaxDynamicSharedMemorySize,
                         (int)LSTM_SMEM);

    init_state_kernel<<<(2 * Bb * Hh + 255) / 256, 256>>>();                 // 0
    conv_all<<<8192, 256>>>(x, Wih0, W1, W2);                                // 1

    // xw0 = x @ Wih0^T + (bih0+bhh0)
    mma_gemm<<<dim3(G4 / 128, M / 128), 256>>>(xb, wih0b, bih0, bhh0,        // 2
                                               xw, nullptr, M, G4, 128);
    // fused 2-layer recurrence (Wih1 GEMM folded in)
    lstm_fused<<<NCTA_LSTM, 128, LSTM_SMEM>>>(Whh0, Wih1, Whh1, bih1, bhh1); // 3

    // MLP
    mma_gemm<<<dim3(512 / 128, M / 128), 256>>>(h1b, w1b, b1, nullptr,       // 4
                                                nullptr, m1b, M, 512, Hh);
    mma_gemm<<<dim3(1024 / 128, M / 128), 256>>>(m1b, w2b, b2, nullptr,      // 5
                                                 nullptr, m2b, M, 1024, 512);
    em_kernel<<<M / 8, 256>>>(m2b, W3, b3, emb);                             // 6

    crf_kernel<<<Bb, 32>>>(emb, tags, st, et, trn);                          // 7
    reduce_kernel<<<1, 256>>>((float*)d_out);                                // 8
}

// round 8
// speedup vs baseline: 1.7927x; 1.0553x over previous
#include <cuda_runtime.h>
#include <cuda_bf16.h>
#include <cstdint>
#include <cstddef>

// ---------------------------------------------------------------------------
// BiLSTM-NER, Round 7: fused 2-layer persistent LSTM (R6 structure) with
//  * 256 threads / 8 warps (4m x 2n warp grid)  -> no spills, 2 warps/SMSP
//  * grid barrier split into 4 independent batch-group barriers (24 CTAs)
//  * startup barrier removed
// FF GEMMs / conv / em / CRF unchanged from R6.
// ---------------------------------------------------------------------------

#define Tt 256
#define Bb 256
#define Hh 384
#define G4 1536   // 4*H
#define INP 100
#define Kc 10
#define NCTA_LSTM 96

typedef __nv_bfloat16 bf16;

// ============================ PTX helpers ==================================
__device__ __forceinline__ uint32_t smem_to_u32(const void* p) {
    uint32_t a;
    asm("{ .reg .u64 t; cvta.to.shared.u64 t, %1; cvt.u32.u64 %0, t; }"
        : "=r"(a) : "l"(p));
    return a;
}
__device__ __forceinline__ void ldsm4(uint32_t* r, uint32_t saddr) {
    asm volatile("ldmatrix.sync.aligned.m8n8.x4.shared.b16 {%0,%1,%2,%3}, [%4];"
        : "=r"(r[0]), "=r"(r[1]), "=r"(r[2]), "=r"(r[3]) : "r"(saddr));
}
__device__ __forceinline__ void mma_bf16(float* c, const uint32_t* a, const uint32_t* b) {
    asm volatile(
        "mma.sync.aligned.m16n8k16.row.col.f32.bf16.bf16.f32 "
        "{%0,%1,%2,%3}, {%4,%5,%6,%7}, {%8,%9}, {%0,%1,%2,%3};"
        : "+f"(c[0]), "+f"(c[1]), "+f"(c[2]), "+f"(c[3])
        : "r"(a[0]), "r"(a[1]), "r"(a[2]), "r"(a[3]), "r"(b[0]), "r"(b[1]));
}
#define CP_ASYNC16(sa, ga) \
    asm volatile("cp.async.cg.shared.global [%0], [%1], 16;" \
                 :: "r"(sa), "l"(ga) : "memory")
#define CP_COMMIT() asm volatile("cp.async.commit_group;" ::: "memory")
#define CP_WAIT0()  asm volatile("cp.async.wait_group 0;" ::: "memory")

__device__ __forceinline__ float tanh_ap(float x) {
    float y; asm("tanh.approx.f32 %0, %1;" : "=f"(y) : "f"(x)); return y;
}
__device__ __forceinline__ float sig_ap(float x) {
    return fmaf(tanh_ap(0.5f * x), 0.5f, 0.5f);
}

// ------------------------- scratch (device globals) ------------------------
__device__ float g_xw[(size_t)Tt * Bb * G4];       // layer-0 gate pre-acts (fp32)
__device__ bf16  g_xb[(size_t)Tt * Bb * 128];      // x padded to K=128, bf16
__device__ bf16  g_h1b[(size_t)Tt * Bb * Hh];      // layer1 outputs (bf16)
__device__ bf16  g_m1b[(size_t)Tt * Bb * 512];     // MLP hidden 1 (bf16)
__device__ bf16  g_m2b[(size_t)Tt * Bb * 1024];    // MLP hidden 2 (bf16)
__device__ float g_em[(size_t)Tt * Bb * Kc];       // emissions (fp32)
__device__ bf16  g_wih0b[1536 * 128];              // Wih0 padded K=128
__device__ bf16  g_w1b[512 * 384];
__device__ bf16  g_w2b[1024 * 512];
__device__ bf16  g_h0buf[2 * Bb * Hh];             // recurrent h0 state (bf16)
__device__ bf16  g_h1buf[2 * Bb * Hh];             // recurrent h1 state (bf16)
__device__ float g_partial[Bb];

// 4 independent barrier groups (counters/gens on separate 256B lines)
__device__ unsigned int          g_barcnt4[4 * 64];
__device__ volatile unsigned int g_bargen4[4 * 64];

// ------------------------------ init state --------------------------------
__global__ void init_state_kernel() {
    int i = blockIdx.x * blockDim.x + threadIdx.x;
    if (i < 2 * Bb * Hh) {
        g_h0buf[i] = __float2bfloat16(0.f);
        g_h1buf[i] = __float2bfloat16(0.f);
    }
    if (i < 4 * 64) { g_barcnt4[i] = 0u; g_bargen4[i] = 0u; }
}

// ---------------------- merged bf16 conversions ----------------------------
#define S0 (65536 * 128)
#define S1 (1536 * 128)
#define S3 (512 * 384)
#define S4 (1024 * 512)
__global__ __launch_bounds__(256) void conv_all(
    const float* __restrict__ x, const float* __restrict__ Wih0,
    const float* __restrict__ W1, const float* __restrict__ W2)
{
    const int total = S0 + S1 + S3 + S4;
    for (int i = blockIdx.x * blockDim.x + threadIdx.x; i < total;
         i += gridDim.x * blockDim.x) {
        if (i < S0) {
            int r = i >> 7, c = i & 127;
            g_xb[i] = (c < INP) ? __float2bfloat16(x[(size_t)r * INP + c])
                                : __float2bfloat16(0.f);
        } else if (i < S0 + S1) {
            int j = i - S0;
            int r = j >> 7, c = j & 127;
            g_wih0b[j] = (c < INP) ? __float2bfloat16(Wih0[(size_t)r * INP + c])
                                   : __float2bfloat16(0.f);
        } else if (i < S0 + S1 + S3) {
            int j = i - S0 - S1;
            g_w1b[j] = __float2bfloat16(W1[j]);
        } else {
            int j = i - S0 - S1 - S3;
            g_w2b[j] = __float2bfloat16(W2[j]);
        }
    }
}

// ------------------ per-batch-group grid barrier (24 CTAs) ------------------
__device__ __forceinline__ void group_barrier(int grp) {
    __threadfence();
    __syncthreads();
    if (threadIdx.x == 0) {
        const int s = grp * 64;
        unsigned int gen = g_bargen4[s];
        if (atomicAdd(&g_barcnt4[s], 1u) == 23u) {
            g_barcnt4[s] = 0u;
            __threadfence();
            g_bargen4[s] = gen + 1u;
        } else {
            while (g_bargen4[s] == gen) { }
        }
    }
    __syncthreads();
}

// ======================== HMMA feed-forward GEMM (R3) ======================
__global__ __launch_bounds__(256) void mma_gemm(
    const bf16* __restrict__ A, const bf16* __restrict__ B,
    const float* __restrict__ bias1, const float* __restrict__ bias2,
    float* __restrict__ Cf, bf16* __restrict__ Cb,
    int M, int N, int K)
{
    __shared__ __align__(16) bf16 smA[2][128 * 40];
    __shared__ __align__(16) bf16 smB[2][128 * 40];

    const int tid = threadIdx.x;
    const int lane = tid & 31;
    const int wid = tid >> 5;
    const int wm = wid & 3;
    const int wn = wid >> 2;
    const int m0 = blockIdx.y * 128;
    const int n0 = blockIdx.x * 128;

    const uint32_t saddrA[2] = { smem_to_u32(smA[0]), smem_to_u32(smA[1]) };
    const uint32_t saddrB[2] = { smem_to_u32(smB[0]), smem_to_u32(smB[1]) };

    float acc[2][8][4];
#pragma unroll
    for (int i = 0; i < 2; i++)
#pragma unroll
        for (int j = 0; j < 8; j++)
#pragma unroll
            for (int q = 0; q < 4; q++) acc[i][j][q] = 0.f;

    const uint32_t a_off =
        (uint32_t)(((wm * 32 + (lane & 15)) * 40 + (lane >> 4) * 8) * 2);
    uint32_t b_off[4];
#pragma unroll
    for (int jp = 0; jp < 4; jp++)
        b_off[jp] = (uint32_t)(((wn * 64 + jp * 16 + (lane & 7) + ((lane >> 4) << 3)) * 40
                                + ((lane >> 3) & 1) * 8) * 2);

    const int lrow = tid >> 2;
    const int lc   = tid & 3;

    const int nkt = K >> 5;
#pragma unroll
    for (int it = 0; it < 2; it++) {
        int row = lrow + it * 64;
        uint32_t d = (uint32_t)((row * 40 + lc * 8) * 2);
        CP_ASYNC16(saddrA[0] + d, A + (size_t)(m0 + row) * K + lc * 8);
        CP_ASYNC16(saddrB[0] + d, B + (size_t)(n0 + row) * K + lc * 8);
    }
    CP_COMMIT();

    for (int kt = 0; kt < nkt; kt++) {
        CP_WAIT0();
        __syncthreads();
        if (kt + 1 < nkt) {
            int s = (kt + 1) & 1;
            int k0 = (kt + 1) * 32;
#pragma unroll
            for (int it = 0; it < 2; it++) {
                int row = lrow + it * 64;
                uint32_t d = (uint32_t)((row * 40 + lc * 8) * 2);
                CP_ASYNC16(saddrA[s] + d, A + (size_t)(m0 + row) * K + k0 + lc * 8);
                CP_ASYNC16(saddrB[s] + d, B + (size_t)(n0 + row) * K + k0 + lc * 8);
            }
        }
        CP_COMMIT();

        const uint32_t sa = saddrA[kt & 1];
        const uint32_t sb = saddrB[kt & 1];
#pragma unroll
        for (int kk = 0; kk < 2; kk++) {
            uint32_t a[2][4], b[4][4];
            ldsm4(a[0], sa + a_off + kk * 32);
            ldsm4(a[1], sa + a_off + 1280 + kk * 32);
#pragma unroll
            for (int jp = 0; jp < 4; jp++)
                ldsm4(b[jp], sb + b_off[jp] + kk * 32);
#pragma unroll
            for (int mt = 0; mt < 2; mt++)
#pragma unroll
                for (int j = 0; j < 8; j++)
                    mma_bf16(acc[mt][j], a[mt], &b[j >> 1][(j & 1) * 2]);
        }
        __syncthreads();
    }

#pragma unroll
    for (int mt = 0; mt < 2; mt++)
#pragma unroll
        for (int j = 0; j < 8; j++)
#pragma unroll
            for (int p = 0; p < 2; p++) {
                int row = m0 + wm * 32 + mt * 16 + (lane >> 2) + p * 8;
                int col = n0 + wn * 64 + j * 8 + (lane & 3) * 2;
                float bb0 = bias1[col], bb1 = bias1[col + 1];
                if (bias2) { bb0 += bias2[col]; bb1 += bias2[col + 1]; }
                float v0 = acc[mt][j][p * 2] + bb0;
                float v1 = acc[mt][j][p * 2 + 1] + bb1;
                if (Cf) {
                    *(float2*)(Cf + (size_t)row * N + col) = make_float2(v0, v1);
                } else {
                    *(__nv_bfloat162*)(Cb + (size_t)row * N + col) =
                        __floats2bfloat162_rn(v0, v1);
                }
            }
}

// ================== fused 2-layer persistent LSTM ==========================
// 96 CTAs (4 batch x 24 colgroups), 256 threads = 8 warps (4m x 2n-half).
// Warp (wm, wn): 16 batch rows x 32 n-cols (4 gates x 8 h-cols, hc half wn).
// Interval t: L0 step t (h0(t-1), xw0(t), Whh0) and L1 step t-1
// (h0(t-1)@Wih1 + h1(t-2)@Whh1 + bias). One shared A tile in SMEM.
__device__ __forceinline__ void mma_pass24(
    float (*acc)[4], uint32_t a_base, uint32_t w_base,
    uint32_t a_off, uint32_t b_off0, uint32_t b_off1)
{
#pragma unroll 6
    for (int kt = 0; kt < 24; kt++) {
        uint32_t koff = (uint32_t)(kt * 32);
        uint32_t a[4], b0[4], b1[4];
        ldsm4(a, a_base + a_off + koff);
        ldsm4(b0, w_base + b_off0 + koff);
        ldsm4(b1, w_base + b_off1 + koff);
        mma_bf16(acc[0], a, &b0[0]);
        mma_bf16(acc[1], a, &b0[2]);
        mma_bf16(acc[2], a, &b1[0]);
        mma_bf16(acc[3], a, &b1[2]);
    }
}

__global__ __launch_bounds__(256) void lstm_fused(
    const float* __restrict__ Whh0, const float* __restrict__ Wih1,
    const float* __restrict__ Whh1, const float* __restrict__ bih1,
    const float* __restrict__ bhh1)
{
    extern __shared__ bf16 dsm[];
    bf16* W0sm  = dsm;                    // Whh0 slice  (64n x 392)
    bf16* Wi1sm = dsm + 64 * 392;         // Wih1 slice
    bf16* W1sm  = dsm + 2 * 64 * 392;     // Whh1 slice
    bf16* Asm   = dsm + 3 * 64 * 392;     // shared A tile (64 x 392)
    const uint32_t w0base  = smem_to_u32(W0sm);
    const uint32_t wi1base = smem_to_u32(Wi1sm);
    const uint32_t w1base  = smem_to_u32(W1sm);
    const uint32_t abase   = smem_to_u32(Asm);

    const int tid = threadIdx.x;
    const int lane = tid & 31;
    const int wid = tid >> 5;
    const int wm = wid & 3;              // 16-row m tile
    const int wn = wid >> 2;             // h-col half (0/1)
    const int bx = blockIdx.x & 3;
    const int by = blockIdx.x >> 2;
    const int b0 = bx * 64;
    const int c0 = by * 16;

    // ---- load 3 resident W slices: [n][k], n = g*16+hc
    for (int idx = tid; idx < 64 * 384; idx += 256) {
        int n = idx / 384, k = idx - n * 384;
        int g = n >> 4, hc = n & 15;
        size_t grow = (size_t)(g * Hh + c0 + hc) * Hh + k;
        int d = n * 392 + k;
        W0sm[d]  = __float2bfloat16(Whh0[grow]);
        Wi1sm[d] = __float2bfloat16(Wih1[grow]);
        W1sm[d]  = __float2bfloat16(Whh1[grow]);
    }

    // A ldsm: rows wm*16 + (lane&15)
    const uint32_t a_off =
        (uint32_t)(((wm * 16 + (lane & 15)) * 392 + (lane >> 4) * 8) * 2);
    // B ldsm: e-th pair covers gates 2e,2e+1; rows g*16 + wn*8 + (lane&7)
    const uint32_t b_k = ((lane >> 3) & 1) * 8;
    const uint32_t b_off0 =
        (uint32_t)((((0 + (lane >> 4)) * 16 + wn * 8 + (lane & 7)) * 392 + b_k) * 2);
    const uint32_t b_off1 =
        (uint32_t)((((2 + (lane >> 4)) * 16 + wn * 8 + (lane & 7)) * 392 + b_k) * 2);

    const int prow = lane >> 2;          // 0..7
    const int pcol = (lane & 3) * 2;     // 0,2,4,6
    const int colg = c0 + wn * 8 + pcol; // this thread's h-col pair

    // layer-1 bias (bih1 + bhh1)
    float bi1[4][2];
#pragma unroll
    for (int g = 0; g < 4; g++)
#pragma unroll
        for (int q = 0; q < 2; q++)
            bi1[g][q] = bih1[g * Hh + colg + q] + bhh1[g * Hh + colg + q];

    float cst0[4], cst1[4];
#pragma unroll
    for (int i = 0; i < 4; i++) { cst0[i] = 0.f; cst1[i] = 0.f; }

    // no startup barrier: W slices are CTA-private; h buffers zeroed by the
    // preceding kernel (stream order guarantees visibility).

    for (int t = 0; t <= Tt; t++) {
        const int ph = t & 1;
        const bool doL0 = (t < Tt);
        const bool doL1 = (t >= 1);

        // ---- load A = h0(t-1) tile (shared by L0 recurrence and L1 input)
        {
            const bf16* hprev0 = g_h0buf + (size_t)ph * Bb * Hh;
#pragma unroll
            for (int it = 0; it < 12; it++) {
                int idx = tid + it * 256;
                int row = idx / 48, c = idx - row * 48;
                CP_ASYNC16(abase + (uint32_t)((row * 392 + c * 8) * 2),
                           hprev0 + (size_t)(b0 + row) * Hh + c * 8);
            }
            CP_COMMIT();
        }

        // ---- xw0(t) fragments for L0 pointwise (hide LDG under cp wait)
        float2 xv[4][2];
        if (doL0) {
            const float* xw = g_xw + (size_t)t * Bb * G4;
#pragma unroll
            for (int g = 0; g < 4; g++)
#pragma unroll
                for (int p = 0; p < 2; p++) {
                    int brow = b0 + wm * 16 + prow + p * 8;
                    xv[g][p] = *(const float2*)(xw + (size_t)brow * G4 + g * Hh + colg);
                }
        }

        CP_WAIT0();
        __syncthreads();

        float accL0[4][4], accL1[4][4];
#pragma unroll
        for (int j = 0; j < 4; j++)
#pragma unroll
            for (int q = 0; q < 4; q++) { accL0[j][q] = 0.f; accL1[j][q] = 0.f; }

        if (doL0) mma_pass24(accL0, abase, w0base,  a_off, b_off0, b_off1);
        if (doL1) mma_pass24(accL1, abase, wi1base, a_off, b_off0, b_off1);
        __syncthreads();    // everyone done reading Asm

        // ---- issue A = h1(t-2) tile load; overlaps L0 pointwise
        if (doL1) {
            const bf16* hprev1 = g_h1buf + (size_t)ph * Bb * Hh;
#pragma unroll
            for (int it = 0; it < 12; it++) {
                int idx = tid + it * 256;
                int row = idx / 48, c = idx - row * 48;
                CP_ASYNC16(abase + (uint32_t)((row * 392 + c * 8) * 2),
                           hprev1 + (size_t)(b0 + row) * Hh + c * 8);
            }
            CP_COMMIT();
        }

        // ---- L0 pointwise: h0(t) -> h0buf[ph^1]
        if (doL0) {
            bf16* hnext0 = g_h0buf + (size_t)(ph ^ 1) * Bb * Hh;
#pragma unroll
            for (int p = 0; p < 2; p++) {
                int brow = b0 + wm * 16 + prow + p * 8;
                float hnv[2];
#pragma unroll
                for (int q = 0; q < 2; q++) {
                    float xi = q ? xv[0][p].y : xv[0][p].x;
                    float xf = q ? xv[1][p].y : xv[1][p].x;
                    float xg = q ? xv[2][p].y : xv[2][p].x;
                    float xo = q ? xv[3][p].y : xv[3][p].x;
                    float i_ = sig_ap(accL0[0][p * 2 + q] + xi);
                    float f_ = sig_ap(accL0[1][p * 2 + q] + xf);
                    float g_ = tanh_ap(accL0[2][p * 2 + q] + xg);
                    float o_ = sig_ap(accL0[3][p * 2 + q] + xo);
                    float cn = f_ * cst0[p * 2 + q] + i_ * g_;
                    cst0[p * 2 + q] = cn;
                    hnv[q] = o_ * tanh_ap(cn);
                }
                *(__nv_bfloat162*)(hnext0 + (size_t)brow * Hh + colg) =
                    __floats2bfloat162_rn(hnv[0], hnv[1]);
            }
        }

        // ---- L1 recurrence mma + pointwise: h1(t-1)
        if (doL1) {
            CP_WAIT0();
            __syncthreads();
            mma_pass24(accL1, abase, w1base, a_off, b_off0, b_off1);

            bf16* hnext1 = g_h1buf + (size_t)(ph ^ 1) * Bb * Hh;
            bf16* houtp  = g_h1b + (size_t)(t - 1) * Bb * Hh;
#pragma unroll
            for (int p = 0; p < 2; p++) {
                int brow = b0 + wm * 16 + prow + p * 8;
                float hnv[2];
#pragma unroll
                for (int q = 0; q < 2; q++) {
                    float i_ = sig_ap(accL1[0][p * 2 + q] + bi1[0][q]);
                    float f_ = sig_ap(accL1[1][p * 2 + q] + bi1[1][q]);
                    float g_ = tanh_ap(accL1[2][p * 2 + q] + bi1[2][q]);
                    float o_ = sig_ap(accL1[3][p * 2 + q] + bi1[3][q]);
                    float cn = f_ * cst1[p * 2 + q] + i_ * g_;
                    cst1[p * 2 + q] = cn;
                    hnv[q] = o_ * tanh_ap(cn);
                }
                __nv_bfloat162 hh = __floats2bfloat162_rn(hnv[0], hnv[1]);
                *(__nv_bfloat162*)(hnext1 + (size_t)brow * Hh + colg) = hh;
                *(__nv_bfloat162*)(houtp + (size_t)brow * Hh + colg) = hh;
            }
        }

        group_barrier(bx);
    }
}

// ------------------------- emissions (N=10 skinny GEMM) --------------------
__global__ __launch_bounds__(256) void em_kernel(
    const bf16* __restrict__ A, const float* __restrict__ W3,
    const float* __restrict__ b3, float* __restrict__ em)
{
    int row  = blockIdx.x * (blockDim.x >> 5) + (threadIdx.x >> 5);
    int lane = threadIdx.x & 31;
    float acc[Kc];
#pragma unroll
    for (int j = 0; j < Kc; j++) acc[j] = 0.f;
    const __nv_bfloat162* ar = (const __nv_bfloat162*)(A + (size_t)row * 1024);
    for (int k2 = lane; k2 < 512; k2 += 32) {
        float2 a = __bfloat1622float2(ar[k2]);
#pragma unroll
        for (int j = 0; j < Kc; j++) {
            acc[j] += a.x * W3[j * 1024 + 2 * k2] + a.y * W3[j * 1024 + 2 * k2 + 1];
        }
    }
#pragma unroll
    for (int j = 0; j < Kc; j++) {
#pragma unroll
        for (int off = 16; off; off >>= 1)
            acc[j] += __shfl_xor_sync(0xffffffffu, acc[j], off);
    }
    if (lane == 0) {
#pragma unroll
        for (int j = 0; j < Kc; j++) em[(size_t)row * Kc + j] = acc[j] + b3[j];
    }
}

// ------------------------------ CRF ----------------------------------------
__global__ __launch_bounds__(32) void crf_kernel(
    const float* __restrict__ em, const int* __restrict__ tags,
    const float* __restrict__ start_t, const float* __restrict__ end_t,
    const float* __restrict__ trans)
{
    const int bp   = blockIdx.x;
    const int lane = threadIdx.x;
    const float NEG = -1e30f;

    float tr[Kc];
    int cl = (lane < Kc) ? lane : 0;
#pragma unroll
    for (int i = 0; i < Kc; i++) tr[i] = trans[i * Kc + cl];

    float a = (lane < Kc) ? (start_t[lane] + em[((size_t)bp * Tt) * Kc + lane]) : NEG;

    for (int tp = 1; tp < Tt; tp++) {
        float e = (lane < Kc) ? em[((size_t)bp * Tt + tp) * Kc + lane] : 0.f;
        float v[Kc];
        float m = NEG;
#pragma unroll
        for (int i = 0; i < Kc; i++) {
            float ai = __shfl_sync(0xffffffffu, a, i);
            v[i] = ai + tr[i];
            m = fmaxf(m, v[i]);
        }
        float s = 0.f;
#pragma unroll
        for (int i = 0; i < Kc; i++) s += __expf(v[i] - m);
        float an = m + __logf(s) + e;
        a = (lane < Kc) ? an : NEG;
    }

    float z = (lane < Kc) ? (a + end_t[lane]) : NEG;
    float zmax = z;
#pragma unroll
    for (int off = 16; off; off >>= 1)
        zmax = fmaxf(zmax, __shfl_xor_sync(0xffffffffu, zmax, off));
    float zs = (lane < Kc) ? __expf(z - zmax) : 0.f;
#pragma unroll
    for (int off = 16; off; off >>= 1)
        zs += __shfl_xor_sync(0xffffffffu, zs, off);
    float logZ = zmax + __logf(zs);

    if (lane == 0) {
        int prev = tags[(size_t)bp * Tt];
        float score = start_t[prev] + em[((size_t)bp * Tt) * Kc + prev];
        for (int tp = 1; tp < Tt; tp++) {
            int tg = tags[(size_t)bp * Tt + tp];
            score += trans[prev * Kc + tg] + em[((size_t)bp * Tt + tp) * Kc + tg];
            prev = tg;
        }
        score += end_t[prev];
        g_partial[bp] = logZ - score;
    }
}

__global__ __launch_bounds__(256) void reduce_kernel(float* __restrict__ out)
{
    __shared__ float sh[256];
    int i = threadIdx.x;
    sh[i] = g_partial[i];
    __syncthreads();
#pragma unroll
    for (int s = 128; s; s >>= 1) {
        if (i < s) sh[i] += sh[i + s];
        __syncthreads();
    }
    if (i == 0) out[0] = sh[0];
}

// ------------------------------ launch -------------------------------------
extern "C" void kernel_launch(void* const* d_in, const int* in_sizes, int n_in,
                              void* d_out, int out_size)
{
    (void)in_sizes; (void)n_in; (void)out_size;
    const float* x    = (const float*)d_in[0];
    const int*   tags = (const int*)d_in[2];
    const float* Wih0 = (const float*)d_in[3];
    const float* Whh0 = (const float*)d_in[4];
    const float* bih0 = (const float*)d_in[5];
    const float* bhh0 = (const float*)d_in[6];
    const float* Wih1 = (const float*)d_in[7];
    const float* Whh1 = (const float*)d_in[8];
    const float* bih1 = (const float*)d_in[9];
    const float* bhh1 = (const float*)d_in[10];
    const float* W1   = (const float*)d_in[11];
    const float* b1   = (const float*)d_in[12];
    const float* W2   = (const float*)d_in[13];
    const float* b2   = (const float*)d_in[14];
    const float* W3   = (const float*)d_in[15];
    const float* b3   = (const float*)d_in[16];
    const float* st   = (const float*)d_in[17];
    const float* et   = (const float*)d_in[18];
    const float* trn  = (const float*)d_in[19];

    float *xw, *emb;
    bf16 *xb, *h1b, *m1b, *m2b, *wih0b, *w1b, *w2b;
    cudaGetSymbolAddress((void**)&xw,    g_xw);
    cudaGetSymbolAddress((void**)&emb,   g_em);
    cudaGetSymbolAddress((void**)&xb,    g_xb);
    cudaGetSymbolAddress((void**)&h1b,   g_h1b);
    cudaGetSymbolAddress((void**)&m1b,   g_m1b);
    cudaGetSymbolAddress((void**)&m2b,   g_m2b);
    cudaGetSymbolAddress((void**)&wih0b, g_wih0b);
    cudaGetSymbolAddress((void**)&w1b,   g_w1b);
    cudaGetSymbolAddress((void**)&w2b,   g_w2b);

    const int M = Tt * Bb;  // 65536
    const size_t LSTM_SMEM = (size_t)(4 * 64 * 392) * sizeof(bf16);  // 200704 B
    cudaFuncSetAttribute(lstm_fused, cudaFuncAttributeMaxDynamicSharedMemorySize,
                         (int)LSTM_SMEM);

    init_state_kernel<<<(2 * Bb * Hh + 255) / 256, 256>>>();                 // 0
    conv_all<<<8192, 256>>>(x, Wih0, W1, W2);                                // 1

    // xw0 = x @ Wih0^T + (bih0+bhh0)
    mma_gemm<<<dim3(G4 / 128, M / 128), 256>>>(xb, wih0b, bih0, bhh0,        // 2
                                               xw, nullptr, M, G4, 128);
    // fused 2-layer recurrence (Wih1 GEMM folded in)
    lstm_fused<<<NCTA_LSTM, 256, LSTM_SMEM>>>(Whh0, Wih1, Whh1, bih1, bhh1); // 3

    // MLP
    mma_gemm<<<dim3(512 / 128, M / 128), 256>>>(h1b, w1b, b1, nullptr,       // 4
                                                nullptr, m1b, M, 512, Hh);
    mma_gemm<<<dim3(1024 / 128, M / 128), 256>>>(m1b, w2b, b2, nullptr,      // 5
                                                 nullptr, m2b, M, 1024, 512);
    em_kernel<<<M / 8, 256>>>(m2b, W3, b3, emb);                             // 6

    crf_kernel<<<Bb, 32>>>(emb, tags, st, et, trn);                          // 7
    reduce_kernel<<<1, 256>>>((float*)d_out);                                // 8
}